// round 9
// baseline (speedup 1.0000x reference)
#include <cuda_runtime.h>
#include <cuda_fp16.h>
#include <cstdint>

// SNNModel: 3-layer LIF SNN, T=10. B=1024, D=4000, H=2048, O=1000.
// HMMA (mma.sync m16n8k16, fp16 in / fp32 accum) with split-precision weights.
// R9: whole network in 3 persistent-tile GEMM launches. Each kernel loops all
// T steps with membrane state + accumulators in registers; spikes written
// straight from MMA fragments; continuous cp.async pipeline across steps.

namespace {
constexpr int kB = 1024, kD = 4000, kH = 2048, kO = 1000, kT = 10;
constexpr int kK1   = 1216;         // per-step K' for layer 1 (3*400 + 16 pad), 19 chunks
constexpr int kLd1  = kT * kK1;     // 12160
constexpr int kNC1  = kLd1 / 64;    // 190 chunks
constexpr int kK2   = 2 * kH;       // 4096
constexpr int kOp   = 1024;
}

// ---------------- persistent device buffers ----------------
__device__ __align__(16) __half g_s1all[(size_t)kT * kB * kH];   // per-step layer-1 spikes
__device__ __align__(16) __half g_s2all[(size_t)kT * kB * kH];   // per-step layer-2 spikes
__device__ __align__(16) __half g_A1c[(size_t)kB * kLd1];   // [B, 10*1216]
__device__ __align__(16) __half g_W1c[(size_t)kH * kLd1];   // [H, 10*1216] (N-major, K contig)
__device__ __align__(16) __half g_W2c[(size_t)kH * kK2];    // [H, 4096]
__device__ __align__(16) __half g_W3c[(size_t)kOp * kK2];   // [1024, 4096]

// ---------------- PTX helpers ----------------
__device__ __forceinline__ uint32_t smem_u32(const void* p) {
    uint32_t a;
    asm("{ .reg .u64 t; cvta.to.shared.u64 t, %1; cvt.u32.u64 %0, t; }" : "=r"(a) : "l"(p));
    return a;
}
__device__ __forceinline__ void cp16(uint32_t dst, const void* src) {
    asm volatile("cp.async.cg.shared.global [%0], [%1], 16;" :: "r"(dst), "l"(src));
}
__device__ __forceinline__ void cp_commit() { asm volatile("cp.async.commit_group;" ::: "memory"); }
__device__ __forceinline__ void cp_wait1()  { asm volatile("cp.async.wait_group 1;" ::: "memory"); }
__device__ __forceinline__ void cp_wait0()  { asm volatile("cp.async.wait_group 0;" ::: "memory"); }
__device__ __forceinline__ void ldmx4(uint32_t& r0, uint32_t& r1, uint32_t& r2, uint32_t& r3,
                                      uint32_t addr) {
    asm volatile("ldmatrix.sync.aligned.m8n8.x4.shared.b16 {%0,%1,%2,%3}, [%4];"
                 : "=r"(r0), "=r"(r1), "=r"(r2), "=r"(r3) : "r"(addr));
}
__device__ __forceinline__ void mma16816(float& c0, float& c1, float& c2, float& c3,
                                         uint32_t a0, uint32_t a1, uint32_t a2, uint32_t a3,
                                         uint32_t b0, uint32_t b1) {
    asm volatile(
        "mma.sync.aligned.m16n8k16.row.col.f32.f16.f16.f32 "
        "{%0,%1,%2,%3}, {%4,%5,%6,%7}, {%8,%9}, {%0,%1,%2,%3};"
        : "+f"(c0), "+f"(c1), "+f"(c2), "+f"(c3)
        : "r"(a0), "r"(a1), "r"(a2), "r"(a3), "r"(b0), "r"(b1));
}
__device__ __forceinline__ uint32_t sw128(uint32_t off) {
    return off ^ ((off >> 3) & 0x70);
}

// ---------------- precompute kernels ----------------
// A1c[m, t*1216 + j] : [xh(400) | xh(400) | xl(400) | pad16]
__global__ void build_xcat(const float* __restrict__ x) {
    long idx = (long)blockIdx.x * blockDim.x + threadIdx.x;
    if (idx >= (long)kB * kLd1) return;
    int m = (int)(idx / kLd1), c = (int)(idx % kLd1);
    int t = c / kK1, j = c % kK1;
    __half o = __float2half_rn(0.0f);
    if (j < 1200) {
        int seg = j / 400, kk = j % 400;
        float xv = x[(long)m * kD + t * 400 + kk];
        __half h = __float2half_rn(xv);
        o = (seg < 2) ? h : __float2half_rn(xv - __half2float(h));
    }
    g_A1c[idx] = o;
}

// W1c per step block: [wh(400) | wl(400) | wh(400) | pad16]. Pairs: xh*wh, xh*wl, xl*wh.
__global__ void build_w1(const float* __restrict__ W) {   // W: [4000, 2048]
    __shared__ float tile[32][33];
    int k0 = blockIdx.x * 32, n0 = blockIdx.y * 32;
    int tx = threadIdx.x & 31, ty = threadIdx.x >> 5;
    for (int i = 0; i < 32; i += 8)
        tile[ty + i][tx] = W[(long)(k0 + ty + i) * kH + n0 + tx];
    __syncthreads();
    for (int i = 0; i < 32; i += 8) {
        int n = n0 + ty + i, kg = k0 + tx;
        int t = kg / 400, kk = kg % 400;
        float v = tile[tx][ty + i];
        __half h = __float2half_rn(v);
        __half l = __float2half_rn(v - __half2float(h));
        long base = (long)n * kLd1 + (long)t * kK1;
        g_W1c[base + kk]       = h;
        g_W1c[base + 400 + kk] = l;
        g_W1c[base + 800 + kk] = h;
    }
}
__global__ void pad_w1() {   // zero cols [1200,1216) of every step block
    long idx = (long)blockIdx.x * blockDim.x + threadIdx.x;   // kH * 10 * 16
    if (idx >= (long)kH * kT * 16) return;
    int n = (int)(idx / (kT * 16)), r = (int)(idx % (kT * 16));
    int t = r / 16, j = 1200 + r % 16;
    g_W1c[(long)n * kLd1 + (long)t * kK1 + j] = __float2half_rn(0.0f);
}

__global__ void build_w2(const float* __restrict__ W) {   // [2048,2048] -> [2048, 4096]
    __shared__ float tile[32][33];
    int k0 = blockIdx.x * 32, n0 = blockIdx.y * 32;
    int tx = threadIdx.x & 31, ty = threadIdx.x >> 5;
    for (int i = 0; i < 32; i += 8)
        tile[ty + i][tx] = W[(long)(k0 + ty + i) * kH + n0 + tx];
    __syncthreads();
    for (int i = 0; i < 32; i += 8) {
        int n = n0 + ty + i, k = k0 + tx;
        float v = tile[tx][ty + i];
        __half h = __float2half_rn(v);
        __half l = __float2half_rn(v - __half2float(h));
        long base = (long)n * kK2;
        g_W2c[base + k] = h; g_W2c[base + kH + k] = l;
    }
}

__global__ void build_w3(const float* __restrict__ W) {   // [2048,1000] -> [1024, 4096]
    __shared__ float tile[32][33];
    int k0 = blockIdx.x * 32, n0 = blockIdx.y * 32;
    int tx = threadIdx.x & 31, ty = threadIdx.x >> 5;
    for (int i = 0; i < 32; i += 8) {
        int n = n0 + tx;
        tile[ty + i][tx] = (n < kO) ? W[(long)(k0 + ty + i) * kO + n] : 0.0f;
    }
    __syncthreads();
    for (int i = 0; i < 32; i += 8) {
        int n = n0 + ty + i, k = k0 + tx;
        float v = tile[tx][ty + i];
        __half h = __float2half_rn(v);
        __half l = __float2half_rn(v - __half2float(h));
        long base = (long)n * kK2;
        g_W3c[base + k] = h; g_W3c[base + kH + k] = l;
    }
}

// ---------------- layer-1 mega kernel: all T steps in one launch ----------------
__global__ __launch_bounds__(256) void snn_l1(
    const __half* __restrict__ A,      // g_A1c
    const __half* __restrict__ Wc,     // g_W1c
    const float* __restrict__ bias,
    __half* __restrict__ s1all)        // [T, B*H]
{
    constexpr uint32_t kABytes = 128 * 128;          // 16384
    constexpr uint32_t kStage = kABytes + 16384;     // 32768

    extern __shared__ __align__(1024) char smem[];
    const uint32_t sbase = smem_u32(smem);
    const int tid = threadIdx.x, wid = tid >> 5, lid = tid & 31;
    const int m0 = blockIdx.y * 128, n0 = blockIdx.x * 128;
    const int wm = (wid >> 2) * 64;
    const int wn = (wid & 3) * 32;
    const int g = lid >> 2, tg = lid & 3;

    float accf[4][4][4];   // running prefix accumulator (never reset)
    float v1[4][4][4];     // membrane potential
#pragma unroll
    for (int i = 0; i < 4; i++)
#pragma unroll
        for (int j = 0; j < 4; j++)
#pragma unroll
            for (int q = 0; q < 4; q++) { accf[i][j][q] = 0.0f; v1[i][j][q] = 0.0f; }

    float bv[4][2];
#pragma unroll
    for (int ni = 0; ni < 4; ni++) {
        int col = n0 + wn + ni * 8 + tg * 2;
        bv[ni][0] = bias[col];
        bv[ni][1] = bias[col + 1];
    }

    auto load_chunk = [&](int c, int b) {
        const int k0 = c * 64;
        const uint32_t abuf = sbase + (uint32_t)b * kStage;
        const uint32_t wbuf = abuf + kABytes;
#pragma unroll
        for (int p = 0; p < 4; p++) {
            int off = (p * 256 + tid) * 16;
            int row = off >> 7, colb = off & 127;
            cp16(abuf + sw128((uint32_t)off), A + (long)(m0 + row) * kLd1 + k0 + (colb >> 1));
        }
#pragma unroll
        for (int p = 0; p < 4; p++) {
            int off = (p * 256 + tid) * 16;
            int row = off >> 7, colb = off & 127;
            cp16(wbuf + sw128((uint32_t)off), Wc + (long)(n0 + row) * kLd1 + k0 + (colb >> 1));
        }
        cp_commit();
    };

    const int a_r = (lid & 7) + ((lid >> 3) & 1) * 8;
    const int a_k = (lid >> 4) * 16;
    const int b_r = (lid & 7) + (lid >> 4) * 8;
    const int b_k = ((lid >> 3) & 1) * 16;

    load_chunk(0, 0);
    load_chunk(1, 1);

    for (int c = 0; c < kNC1; c++) {
        const int b = c % 3;
        if (c + 1 < kNC1) cp_wait1(); else cp_wait0();
        __syncthreads();
        if (c + 2 < kNC1) load_chunk(c + 2, (c + 2) % 3);

        const uint32_t abuf = sbase + (uint32_t)b * kStage;
        const uint32_t wbuf = abuf + kABytes;
#pragma unroll
        for (int ks = 0; ks < 4; ks++) {
            uint32_t af[4][4];
#pragma unroll
            for (int mi = 0; mi < 4; mi++) {
                uint32_t off = (uint32_t)((wm + mi * 16 + a_r) * 128 + ks * 32 + a_k);
                ldmx4(af[mi][0], af[mi][1], af[mi][2], af[mi][3], abuf + sw128(off));
            }
            uint32_t bfr[2][4];
#pragma unroll
            for (int np = 0; np < 2; np++) {
                uint32_t off = (uint32_t)((wn + np * 16 + b_r) * 128 + ks * 32 + b_k);
                ldmx4(bfr[np][0], bfr[np][1], bfr[np][2], bfr[np][3], wbuf + sw128(off));
            }
#pragma unroll
            for (int mi = 0; mi < 4; mi++)
#pragma unroll
                for (int ni = 0; ni < 4; ni++) {
                    const uint32_t* bp = &bfr[ni >> 1][(ni & 1) * 2];
                    mma16816(accf[mi][ni][0], accf[mi][ni][1], accf[mi][ni][2], accf[mi][ni][3],
                             af[mi][0], af[mi][1], af[mi][2], af[mi][3], bp[0], bp[1]);
                }
        }

        // step boundary: LIF in registers, spikes straight to gmem
        if (c % 19 == 18) {
            const int st = c / 19;
            __half* sout = s1all + (size_t)st * kB * kH;
#pragma unroll
            for (int mi = 0; mi < 4; mi++) {
                int row0 = m0 + wm + mi * 16 + g;
#pragma unroll
                for (int ni = 0; ni < 4; ni++) {
                    int col = n0 + wn + ni * 8 + tg * 2;
                    float s[4];
#pragma unroll
                    for (int q = 0; q < 4; q++) {
                        float cc = accf[mi][ni][q] + bv[ni][q & 1];
                        float v = v1[mi][ni][q];
                        v = v + (cc - v) * 0.5f;
                        s[q] = (v >= 1.0f) ? 1.0f : 0.0f;
                        v1[mi][ni][q] = v * (1.0f - s[q]);
                    }
                    *reinterpret_cast<__half2*>(&sout[(long)row0 * kH + col]) =
                        __floats2half2_rn(s[0], s[1]);
                    *reinterpret_cast<__half2*>(&sout[(long)(row0 + 8) * kH + col]) =
                        __floats2half2_rn(s[2], s[3]);
                }
            }
        }
    }
}

// ---------------- fused L2 / L3 mega kernel: all T steps in one launch ----------------
// Persistent (m0, n0) tile. Global chunk index gc: t = gc/64, c = gc%64.
// A = Aall + t*B*2048, k wraps mod 2048 (2-split K-concat). v stays in registers.
// L2 (soutall != null): write spikes per step. L3 (outf != null): write float out at t=T-1.
template <int BM>
__global__ __launch_bounds__(256) void snn_l23(
    const __half* __restrict__ Aall,   // [T, B, 2048]
    const __half* __restrict__ Wc,     // [*, 4096]
    const float* __restrict__ bias,
    __half* __restrict__ soutall,      // nullable: [T, B, N]
    float* __restrict__ outf,          // nullable: [B, N] final step
    int N)
{
    constexpr int MI = BM / 32;
    constexpr uint32_t kABytes = BM * 128;
    constexpr uint32_t kStage = kABytes + 16384;
    constexpr int kNCtot = kT * 64;

    extern __shared__ __align__(1024) char smem[];
    const uint32_t sbase = smem_u32(smem);
    const int tid = threadIdx.x, wid = tid >> 5, lid = tid & 31;
    const int m0 = blockIdx.y * BM, n0 = blockIdx.x * 128;
    const int wm = (wid >> 2) * (16 * MI);
    const int wn = (wid & 3) * 32;
    const int g = lid >> 2, tg = lid & 3;

    float accf[MI][4][4];
    float vst[MI][4][4];
#pragma unroll
    for (int i = 0; i < MI; i++)
#pragma unroll
        for (int j = 0; j < 4; j++)
#pragma unroll
            for (int q = 0; q < 4; q++) { accf[i][j][q] = 0.0f; vst[i][j][q] = 0.0f; }

    float bv[4][2];
#pragma unroll
    for (int ni = 0; ni < 4; ni++) {
        int col = n0 + wn + ni * 8 + tg * 2;
        bv[ni][0] = (col < N) ? bias[col] : 0.0f;
        bv[ni][1] = (col + 1 < N) ? bias[col + 1] : 0.0f;
    }

    auto load_chunk = [&](int gc, int b) {
        const int t = gc >> 6;
        const int ak = (gc & 31) * 64;          // (gc%64)*64 mod 2048
        const int k0 = (gc & 63) * 64;
        const __half* At = Aall + (size_t)t * kB * kH;
        const uint32_t abuf = sbase + (uint32_t)b * kStage;
        const uint32_t wbuf = abuf + kABytes;
#pragma unroll
        for (int p = 0; p < MI; p++) {
            int off = (p * 256 + tid) * 16;
            int row = off >> 7, colb = off & 127;
            cp16(abuf + sw128((uint32_t)off), At + (long)(m0 + row) * kH + ak + (colb >> 1));
        }
#pragma unroll
        for (int p = 0; p < 4; p++) {
            int off = (p * 256 + tid) * 16;
            int row = off >> 7, colb = off & 127;
            cp16(wbuf + sw128((uint32_t)off), Wc + (long)(n0 + row) * kK2 + k0 + (colb >> 1));
        }
        cp_commit();
    };

    const int a_r = (lid & 7) + ((lid >> 3) & 1) * 8;
    const int a_k = (lid >> 4) * 16;
    const int b_r = (lid & 7) + (lid >> 4) * 8;
    const int b_k = ((lid >> 3) & 1) * 16;

    load_chunk(0, 0);
    load_chunk(1, 1);

    for (int gc = 0; gc < kNCtot; gc++) {
        const int b = gc % 3;
        if (gc + 1 < kNCtot) cp_wait1(); else cp_wait0();
        __syncthreads();
        if (gc + 2 < kNCtot) load_chunk(gc + 2, (gc + 2) % 3);

        const uint32_t abuf = sbase + (uint32_t)b * kStage;
        const uint32_t wbuf = abuf + kABytes;
#pragma unroll
        for (int ks = 0; ks < 4; ks++) {
            uint32_t af[MI][4];
#pragma unroll
            for (int mi = 0; mi < MI; mi++) {
                uint32_t off = (uint32_t)((wm + mi * 16 + a_r) * 128 + ks * 32 + a_k);
                ldmx4(af[mi][0], af[mi][1], af[mi][2], af[mi][3], abuf + sw128(off));
            }
            uint32_t bfr[2][4];
#pragma unroll
            for (int np = 0; np < 2; np++) {
                uint32_t off = (uint32_t)((wn + np * 16 + b_r) * 128 + ks * 32 + b_k);
                ldmx4(bfr[np][0], bfr[np][1], bfr[np][2], bfr[np][3], wbuf + sw128(off));
            }
#pragma unroll
            for (int mi = 0; mi < MI; mi++)
#pragma unroll
                for (int ni = 0; ni < 4; ni++) {
                    const uint32_t* bp = &bfr[ni >> 1][(ni & 1) * 2];
                    mma16816(accf[mi][ni][0], accf[mi][ni][1], accf[mi][ni][2], accf[mi][ni][3],
                             af[mi][0], af[mi][1], af[mi][2], af[mi][3], bp[0], bp[1]);
                }
        }

        // step boundary: LIF in registers; reset accumulators for next step
        if ((gc & 63) == 63) {
            const int st = gc >> 6;
            __half* sout = soutall ? soutall + (size_t)st * kB * N : nullptr;
            const bool wfinal = (outf != nullptr) && (st == kT - 1);
#pragma unroll
            for (int mi = 0; mi < MI; mi++) {
                int row0 = m0 + wm + mi * 16 + g;
#pragma unroll
                for (int ni = 0; ni < 4; ni++) {
                    int col = n0 + wn + ni * 8 + tg * 2;
                    float s[4];
#pragma unroll
                    for (int q = 0; q < 4; q++) {
                        float cc = accf[mi][ni][q] + bv[ni][q & 1];
                        float v = vst[mi][ni][q];
                        v = v + (cc - v) * 0.5f;
                        s[q] = (v >= 1.0f) ? 1.0f : 0.0f;
                        vst[mi][ni][q] = v * (1.0f - s[q]);
                        accf[mi][ni][q] = 0.0f;
                    }
                    if (sout) {
                        *reinterpret_cast<__half2*>(&sout[(long)row0 * N + col]) =
                            __floats2half2_rn(s[0], s[1]);
                        *reinterpret_cast<__half2*>(&sout[(long)(row0 + 8) * N + col]) =
                            __floats2half2_rn(s[2], s[3]);
                    }
                    if (wfinal) {
                        if (col < N)     outf[(long)row0 * N + col] = s[0];
                        if (col + 1 < N) outf[(long)row0 * N + col + 1] = s[1];
                        if (col < N)     outf[(long)(row0 + 8) * N + col] = s[2];
                        if (col + 1 < N) outf[(long)(row0 + 8) * N + col + 1] = s[3];
                    }
                }
            }
        }
    }
}

// ---------------- launch ----------------
extern "C" void kernel_launch(void* const* d_in, const int* in_sizes, int n_in,
                              void* d_out, int out_size) {
    const float* x  = (const float*)d_in[0];
    const float* W1 = (const float*)d_in[1];
    const float* b1 = (const float*)d_in[2];
    const float* W2 = (const float*)d_in[3];
    const float* b2 = (const float*)d_in[4];
    const float* W3 = (const float*)d_in[5];
    const float* b3 = (const float*)d_in[6];
    float* out = (float*)d_out;

    __half *s1all, *s2all, *a1c, *w1c, *w2c, *w3c;
    cudaGetSymbolAddress((void**)&s1all, g_s1all);
    cudaGetSymbolAddress((void**)&s2all, g_s2all);
    cudaGetSymbolAddress((void**)&a1c, g_A1c);
    cudaGetSymbolAddress((void**)&w1c, g_W1c);
    cudaGetSymbolAddress((void**)&w2c, g_W2c);
    cudaGetSymbolAddress((void**)&w3c, g_W3c);

    constexpr unsigned kSmem128 = 3u * (128u * 128u + 16384u);   // 98304
    constexpr unsigned kSmem64  = 3u * (64u * 128u + 16384u);    // 73728
    cudaFuncSetAttribute(snn_l1,        cudaFuncAttributeMaxDynamicSharedMemorySize, kSmem128);
    cudaFuncSetAttribute(snn_l23<128>,  cudaFuncAttributeMaxDynamicSharedMemorySize, kSmem128);
    cudaFuncSetAttribute(snn_l23<64>,   cudaFuncAttributeMaxDynamicSharedMemorySize, kSmem64);

    build_xcat<<<(int)(((long)kB * kLd1 + 255) / 256), 256>>>(x);
    build_w1<<<dim3(125, 64), 256>>>(W1);
    pad_w1<<<(int)(((long)kH * kT * 16 + 255) / 256), 256>>>();
    build_w2<<<dim3(64, 64), 256>>>(W2);
    build_w3<<<dim3(64, 32), 256>>>(W3);

    dim3 blk(256);
    dim3 gridH(16, 8);    // N=2048 x M=1024, BM=128
    dim3 gridO(8, 16);    // N=1000 (8 tiles of 128) x M=1024, BM=64

    // whole network: 3 GEMM launches
    snn_l1<<<gridH, blk, kSmem128>>>(a1c, w1c, b1, s1all);
    snn_l23<128><<<gridH, blk, kSmem128>>>(s1all, w2c, b2, s2all, nullptr, kH);
    snn_l23<64><<<gridO, blk, kSmem64>>>(s2all, w3c, b3, nullptr, out, kO);
}